// round 3
// baseline (speedup 1.0000x reference)
#include <cuda_runtime.h>
#include <cstdint>

#define BB   4
#define N1   16384
#define N2   4096
#define CC   128
#define CIN  384
#define CH   256
#define TN   64
#define KC   32
#define SXS  72          // sX / sY row stride in floats: 72 % 32 == 8 -> conflict-free frag loads
#define SWS  264         // sW row stride in floats: 264 % 32 == 8

#define SX_FLOATS   (CIN * SXS)          // 27648
#define SW_FLOATS   (KC * SWS)           // 8448
#define SMEM_MLP_BYTES ((SX_FLOATS + SW_FLOATS + TN) * 4)  // 144640

// ------------------- scratch (device globals; no allocation) -------------------
__device__ float4 g_xyz2n[BB * N2];          // packed xyz2 + |x|^2
__device__ float4 g_w4[BB * N1];             // normalized 3-NN weights
__device__ int4   g_i4[BB * N1];             // 3-NN indices
__device__ float  g_p2t[BB * N2 * CC];       // points2 transposed (B, N2, C)
__device__ float  g_W0t[CIN * CH];           // folded W0, transposed (k, oc)
__device__ float  g_W1t[CH * CH];            // folded W1, transposed (k, oc)
__device__ float  g_b0f[CH];
__device__ float  g_b1f[CH];

// ------------------- helpers -------------------
__device__ __forceinline__ float cvt_tf32(float x) {
    unsigned u;
    asm("cvt.rna.tf32.f32 %0, %1;" : "=r"(u) : "f"(x));
    return __uint_as_float(u);
}

__device__ __forceinline__ void mma8(float* d, const unsigned* a, const unsigned* b) {
    asm("mma.sync.aligned.m16n8k8.row.col.f32.tf32.tf32.f32 "
        "{%0,%1,%2,%3}, {%4,%5,%6,%7}, {%8,%9}, {%0,%1,%2,%3};\n"
        : "+f"(d[0]), "+f"(d[1]), "+f"(d[2]), "+f"(d[3])
        : "r"(a[0]), "r"(a[1]), "r"(a[2]), "r"(a[3]), "r"(b[0]), "r"(b[1]));
}

// ------------------- K1: fold BN into weights, transpose to (k, oc) -------------------
__global__ void fold_kernel(const float* __restrict__ w0, const float* __restrict__ b0,
                            const float* __restrict__ g0, const float* __restrict__ be0,
                            const float* __restrict__ m0, const float* __restrict__ v0,
                            const float* __restrict__ w1, const float* __restrict__ b1,
                            const float* __restrict__ g1, const float* __restrict__ be1,
                            const float* __restrict__ m1, const float* __restrict__ v1) {
    int t = blockIdx.x * blockDim.x + threadIdx.x;
    if (t < CH * CIN) {
        int o = t / CIN, c = t % CIN;
        float s = g0[o] * rsqrtf(v0[o] + 1e-5f);
        g_W0t[c * CH + o] = w0[t] * s;
    }
    if (t < CH * CH) {
        int o = t / CH, c = t % CH;
        float s = g1[o] * rsqrtf(v1[o] + 1e-5f);
        g_W1t[c * CH + o] = w1[t] * s;
    }
    if (t < CH) {
        float s0 = g0[t] * rsqrtf(v0[t] + 1e-5f);
        g_b0f[t] = (b0[t] - m0[t]) * s0 + be0[t];
        float s1 = g1[t] * rsqrtf(v1[t] + 1e-5f);
        g_b1f[t] = (b1[t] - m1[t]) * s1 + be1[t];
    }
}

// ------------------- K2: pack xyz2 with norms -------------------
__global__ void pack_kernel(const float* __restrict__ xyz2) {
    int t = blockIdx.x * blockDim.x + threadIdx.x;
    if (t < BB * N2) {
        float x = xyz2[3 * t], y = xyz2[3 * t + 1], z = xyz2[3 * t + 2];
        g_xyz2n[t] = make_float4(x, y, z, x * x + y * y + z * z);
    }
}

// ------------------- K3: transpose points2 (B,C,N2) -> (B,N2,C) -------------------
__global__ void transpose_kernel(const float* __restrict__ p2) {
    __shared__ float tile[32][33];
    int b = blockIdx.z;
    int nb = blockIdx.x * 32, cb = blockIdx.y * 32;
    int tx = threadIdx.x, ty = threadIdx.y;  // (32, 8)
    #pragma unroll
    for (int i = 0; i < 32; i += 8)
        tile[ty + i][tx] = p2[((size_t)b * CC + cb + ty + i) * N2 + nb + tx];
    __syncthreads();
    #pragma unroll
    for (int i = 0; i < 32; i += 8)
        g_p2t[((size_t)b * N2 + nb + ty + i) * CC + cb + tx] = tile[tx][ty + i];
}

// ------------------- K4: 3-NN top-3 + interpolation weights -------------------
__device__ __forceinline__ void ins3(float s, int j,
                                     float& a0, float& a1, float& a2,
                                     int& i0, int& i1, int& i2) {
    if (s < a2) {
        if (s < a1) {
            a2 = a1; i2 = i1;
            if (s < a0) { a1 = a0; i1 = i0; a0 = s; i0 = j; }
            else        { a1 = s;  i1 = j; }
        } else { a2 = s; i2 = j; }
    }
}

__global__ void __launch_bounds__(256) knn_kernel(const float* __restrict__ xyz1) {
    extern __shared__ float4 sP[];   // N2 entries = 64 KB
    int b = blockIdx.y;
    int t = threadIdx.x;
    for (int i = t; i < N2; i += 256) sP[i] = g_xyz2n[b * N2 + i];
    __syncthreads();

    int q0 = blockIdx.x * 512 + t;
    int q1 = q0 + 256;
    const float* p0 = xyz1 + ((size_t)b * N1 + q0) * 3;
    const float* p1 = xyz1 + ((size_t)b * N1 + q1) * 3;
    float x0 = p0[0], y0 = p0[1], z0 = p0[2];
    float x1 = p1[0], y1 = p1[1], z1 = p1[2];
    float ax0 = -2.f * x0, ay0 = -2.f * y0, az0 = -2.f * z0;
    float ax1 = -2.f * x1, ay1 = -2.f * y1, az1 = -2.f * z1;

    float A0 = 3.0e38f, A1 = 3.0e38f, A2 = 3.0e38f;
    float B0 = 3.0e38f, B1 = 3.0e38f, B2 = 3.0e38f;
    int   I0 = 0, I1 = 0, I2 = 0, J0 = 0, J1 = 0, J2 = 0;

    #pragma unroll 4
    for (int j = 0; j < N2; j++) {
        float4 p = sP[j];
        float s0 = fmaf(ax0, p.x, fmaf(ay0, p.y, fmaf(az0, p.z, p.w)));
        ins3(s0, j, A0, A1, A2, I0, I1, I2);
        float s1 = fmaf(ax1, p.x, fmaf(ay1, p.y, fmaf(az1, p.z, p.w)));
        ins3(s1, j, B0, B1, B2, J0, J1, J2);
    }

    {
        float nq = x0 * x0 + y0 * y0 + z0 * z0;
        float w0 = 1.f / (nq + A0), w1 = 1.f / (nq + A1), w2 = 1.f / (nq + A2);
        float inv = 1.f / (w0 + w1 + w2);
        g_w4[b * N1 + q0] = make_float4(w0 * inv, w1 * inv, w2 * inv, 0.f);
        g_i4[b * N1 + q0] = make_int4(I0, I1, I2, 0);
    }
    {
        float nq = x1 * x1 + y1 * y1 + z1 * z1;
        float w0 = 1.f / (nq + B0), w1 = 1.f / (nq + B1), w2 = 1.f / (nq + B2);
        float inv = 1.f / (w0 + w1 + w2);
        g_w4[b * N1 + q1] = make_float4(w0 * inv, w1 * inv, w2 * inv, 0.f);
        g_i4[b * N1 + q1] = make_int4(J0, J1, J2, 0);
    }
}

// ------------------- K5: fused concat + 2x (GEMM + BN + ReLU) + channel max -------------------
__global__ void __launch_bounds__(256, 1)
mlp_kernel(const float* __restrict__ points1, const float* __restrict__ pb1,
           float* __restrict__ out) {
    extern __shared__ float sm[];
    float* sX   = sm;                              // [384][SXS], tf32-rounded; later reused as sY
    float* sW   = sm + SX_FLOATS;                  // [KC][SWS]
    int*   sOutI = (int*)(sm + SX_FLOATS + SW_FLOATS);  // [TN]

    int b  = blockIdx.y;
    int n0 = blockIdx.x * TN;
    int tid = threadIdx.x;
    int warp = tid >> 5, lane = tid & 31;
    int grp = lane >> 2, tig = lane & 3;
    int Rw = warp * 32;

    // ---- Phase A: build X tile (384 x 64) in smem ----
    for (int idx = tid; idx < CC * TN; idx += 256) {
        int c = idx >> 6, n = idx & 63;
        sX[c * SXS + n]         = cvt_tf32(points1[((size_t)b * CC + c) * N1 + n0 + n]);
        sX[(c + 256) * SXS + n] = cvt_tf32(pb1[((size_t)b * CC + c) * N1 + n0 + n]);
    }
    // fused section rows 128..255 (each warp handles 8 queries; coalesced row gathers)
    for (int qq = 0; qq < 8; qq++) {
        int q = warp * 8 + qq;
        int n = n0 + q;
        float4 wv = g_w4[b * N1 + n];
        int4   iv = g_i4[b * N1 + n];
        const float* r0 = &g_p2t[((size_t)b * N2 + iv.x) * CC];
        const float* r1 = &g_p2t[((size_t)b * N2 + iv.y) * CC];
        const float* r2 = &g_p2t[((size_t)b * N2 + iv.z) * CC];
        #pragma unroll
        for (int i = 0; i < 4; i++) {
            int c = lane + 32 * i;
            float v = wv.x * r0[c] + wv.y * r1[c] + wv.z * r2[c];
            sX[(128 + c) * SXS + q] = cvt_tf32(v);
        }
    }
    __syncthreads();

    // ---- Phase B: GEMM1  y0(256x64) = W0'(256x384) * X ----
    float acc[2][8][4];
    #pragma unroll
    for (int m = 0; m < 2; m++)
        #pragma unroll
        for (int j = 0; j < 8; j++)
            #pragma unroll
            for (int e = 0; e < 4; e++) acc[m][j][e] = 0.f;

    for (int cc = 0; cc < CIN / KC; cc++) {
        int kc = cc * KC;
        for (int idx = tid; idx < KC * CH; idx += 256) {
            int kk = idx >> 8, oc = idx & 255;
            sW[kk * SWS + oc] = cvt_tf32(g_W0t[(kc + kk) * CH + oc]);
        }
        __syncthreads();
        #pragma unroll
        for (int ks = 0; ks < KC / 8; ks++) {
            int k8 = ks * 8;
            unsigned a[2][4], bf[8][2];
            #pragma unroll
            for (int m = 0; m < 2; m++) {
                int rb = Rw + m * 16 + grp;
                const float* w0r = sW + (k8 + tig) * SWS;
                const float* w4r = sW + (k8 + tig + 4) * SWS;
                a[m][0] = __float_as_uint(w0r[rb]);
                a[m][1] = __float_as_uint(w0r[rb + 8]);
                a[m][2] = __float_as_uint(w4r[rb]);
                a[m][3] = __float_as_uint(w4r[rb + 8]);
            }
            const float* x0r = sX + (kc + k8 + tig) * SXS;
            const float* x4r = sX + (kc + k8 + tig + 4) * SXS;
            #pragma unroll
            for (int j = 0; j < 8; j++) {
                int cb = j * 8 + grp;
                bf[j][0] = __float_as_uint(x0r[cb]);
                bf[j][1] = __float_as_uint(x4r[cb]);
            }
            #pragma unroll
            for (int m = 0; m < 2; m++)
                #pragma unroll
                for (int j = 0; j < 8; j++)
                    mma8(acc[m][j], a[m], bf[j]);
        }
        __syncthreads();
    }

    // ---- epilogue 1: bias + ReLU -> sY (reuses sX region) ----
    float bz[4];
    #pragma unroll
    for (int i = 0; i < 4; i++) bz[i] = g_b0f[Rw + grp + 8 * i];
    float* sY = sm;   // [256][SXS]
    #pragma unroll
    for (int m = 0; m < 2; m++)
        #pragma unroll
        for (int j = 0; j < 8; j++) {
            int r0 = Rw + 16 * m + grp;
            int col = 8 * j + 2 * tig;
            sY[r0 * SXS + col]           = cvt_tf32(fmaxf(acc[m][j][0] + bz[2 * m], 0.f));
            sY[r0 * SXS + col + 1]       = cvt_tf32(fmaxf(acc[m][j][1] + bz[2 * m], 0.f));
            sY[(r0 + 8) * SXS + col]     = cvt_tf32(fmaxf(acc[m][j][2] + bz[2 * m + 1], 0.f));
            sY[(r0 + 8) * SXS + col + 1] = cvt_tf32(fmaxf(acc[m][j][3] + bz[2 * m + 1], 0.f));
        }

    // ---- Phase C: GEMM2  y1(256x64) = W1'(256x256) * y0 ----
    float ac2[2][8][4];
    #pragma unroll
    for (int m = 0; m < 2; m++)
        #pragma unroll
        for (int j = 0; j < 8; j++)
            #pragma unroll
            for (int e = 0; e < 4; e++) ac2[m][j][e] = 0.f;

    for (int cc = 0; cc < CH / KC; cc++) {
        int kc = cc * KC;
        // note: first stage's writes to sW are safe; epilogue-1 wrote only sY, and
        // no thread reads sW until after the stage __syncthreads below.
        __syncthreads();
        for (int idx = tid; idx < KC * CH; idx += 256) {
            int kk = idx >> 8, oc = idx & 255;
            sW[kk * SWS + oc] = cvt_tf32(g_W1t[(kc + kk) * CH + oc]);
        }
        __syncthreads();
        #pragma unroll
        for (int ks = 0; ks < KC / 8; ks++) {
            int k8 = ks * 8;
            unsigned a[2][4], bf[8][2];
            #pragma unroll
            for (int m = 0; m < 2; m++) {
                int rb = Rw + m * 16 + grp;
                const float* w0r = sW + (k8 + tig) * SWS;
                const float* w4r = sW + (k8 + tig + 4) * SWS;
                a[m][0] = __float_as_uint(w0r[rb]);
                a[m][1] = __float_as_uint(w0r[rb + 8]);
                a[m][2] = __float_as_uint(w4r[rb]);
                a[m][3] = __float_as_uint(w4r[rb + 8]);
            }
            const float* y0r = sY + (kc + k8 + tig) * SXS;
            const float* y4r = sY + (kc + k8 + tig + 4) * SXS;
            #pragma unroll
            for (int j = 0; j < 8; j++) {
                int cb = j * 8 + grp;
                bf[j][0] = __float_as_uint(y0r[cb]);
                bf[j][1] = __float_as_uint(y4r[cb]);
            }
            #pragma unroll
            for (int m = 0; m < 2; m++)
                #pragma unroll
                for (int j = 0; j < 8; j++)
                    mma8(ac2[m][j], a[m], bf[j]);
        }
    }
    __syncthreads();

    // ---- epilogue 2: bias + ReLU + max over 256 channels ----
    float bz1[4];
    #pragma unroll
    for (int i = 0; i < 4; i++) bz1[i] = g_b1f[Rw + grp + 8 * i];

    if (tid < TN) sOutI[tid] = 0;   // ReLU output >= 0, so int 0 == 0.0f is a valid identity
    __syncthreads();

    #pragma unroll
    for (int j = 0; j < 8; j++) {
        #pragma unroll
        for (int e = 0; e < 2; e++) {
            int col = 8 * j + 2 * tig + e;
            float v =            fmaxf(ac2[0][j][e]     + bz1[0], 0.f);
            v = fmaxf(v,         fmaxf(ac2[0][j][e + 2] + bz1[1], 0.f));
            v = fmaxf(v,         fmaxf(ac2[1][j][e]     + bz1[2], 0.f));
            v = fmaxf(v,         fmaxf(ac2[1][j][e + 2] + bz1[3], 0.f));
            v = fmaxf(v, __shfl_xor_sync(0xffffffffu, v, 4));
            v = fmaxf(v, __shfl_xor_sync(0xffffffffu, v, 8));
            v = fmaxf(v, __shfl_xor_sync(0xffffffffu, v, 16));
            if (grp == 0) atomicMax(&sOutI[col], __float_as_int(v));
        }
    }
    __syncthreads();
    if (tid < TN) out[(size_t)b * N1 + n0 + tid] = __int_as_float(sOutI[tid]);
}

// ------------------- launch -------------------
extern "C" void kernel_launch(void* const* d_in, const int* in_sizes, int n_in,
                              void* d_out, int out_size) {
    const float* xyz1    = (const float*)d_in[0];
    const float* xyz2    = (const float*)d_in[1];
    const float* points2 = (const float*)d_in[2];
    const float* points1 = (const float*)d_in[3];
    const float* pb1     = (const float*)d_in[4];
    const float* w0  = (const float*)d_in[5];
    const float* b0  = (const float*)d_in[6];
    const float* g0  = (const float*)d_in[7];
    const float* be0 = (const float*)d_in[8];
    const float* m0  = (const float*)d_in[9];
    const float* v0  = (const float*)d_in[10];
    const float* w1  = (const float*)d_in[11];
    const float* b1  = (const float*)d_in[12];
    const float* g1  = (const float*)d_in[13];
    const float* be1 = (const float*)d_in[14];
    const float* m1  = (const float*)d_in[15];
    const float* v1  = (const float*)d_in[16];
    float* out = (float*)d_out;

    cudaFuncSetAttribute(knn_kernel, cudaFuncAttributeMaxDynamicSharedMemorySize,
                         (int)(N2 * sizeof(float4)));
    cudaFuncSetAttribute(mlp_kernel, cudaFuncAttributeMaxDynamicSharedMemorySize,
                         SMEM_MLP_BYTES);

    fold_kernel<<<(CH * CIN + 255) / 256, 256>>>(w0, b0, g0, be0, m0, v0,
                                                 w1, b1, g1, be1, m1, v1);
    pack_kernel<<<(BB * N2 + 255) / 256, 256>>>(xyz2);
    transpose_kernel<<<dim3(N2 / 32, CC / 32, BB), dim3(32, 8)>>>(points2);
    knn_kernel<<<dim3(N1 / 512, BB), 256, N2 * sizeof(float4)>>>(xyz1);
    mlp_kernel<<<dim3(N1 / TN, BB), 256, SMEM_MLP_BYTES>>>(points1, pb1, out);
}

// round 5
// speedup vs baseline: 2.0833x; 2.0833x over previous
#include <cuda_runtime.h>
#include <cstdint>

#define BB   4
#define N1   16384
#define N2   4096
#define CC   128
#define CIN  384
#define CH   256
#define TN   64
#define KC   32
#define SXS  72          // sX / sY row stride in floats: 72 % 32 == 8 -> conflict-free frag loads
#define SWS  264         // sW row stride in floats: 264 % 32 == 8
#define SEG  8
#define SEGN (N2 / SEG)  // 512

#define SX_FLOATS   (CIN * SXS)          // 27648
#define SW_FLOATS   (KC * SWS)           // 8448  (one buffer)
#define NBUF        3
#define NCHUNK      20                   // 12 for GEMM1 + 8 for GEMM2
#define SMEM_MLP_BYTES ((SX_FLOATS + NBUF * SW_FLOATS + TN) * 4)  // 212224

// ------------------- scratch (device globals; no allocation) -------------------
__device__ float4 g_xyz2n[BB * N2];          // packed xyz2 + |x|^2
__device__ float4 g_w4[BB * N1];             // normalized 3-NN weights
__device__ int4   g_i4[BB * N1];             // 3-NN indices
__device__ float4 g_pd[BB * SEG * N1];       // per-segment partial top-3 scores
__device__ int4   g_pi[BB * SEG * N1];       // per-segment partial top-3 indices
__device__ float  g_p2t[BB * N2 * CC];       // points2 transposed (B, N2, C)
__device__ float  g_W0t[CIN * CH];           // folded W0, transposed (k, oc), tf32-rounded
__device__ float  g_W1t[CH * CH];            // folded W1, transposed (k, oc), tf32-rounded
__device__ float  g_b0f[CH];
__device__ float  g_b1f[CH];

// ------------------- helpers -------------------
__device__ __forceinline__ float cvt_tf32(float x) {
    unsigned u;
    asm("cvt.rna.tf32.f32 %0, %1;" : "=r"(u) : "f"(x));
    return __uint_as_float(u);
}

__device__ __forceinline__ void mma8(float* d, const unsigned* a, const unsigned* b) {
    asm("mma.sync.aligned.m16n8k8.row.col.f32.tf32.tf32.f32 "
        "{%0,%1,%2,%3}, {%4,%5,%6,%7}, {%8,%9}, {%0,%1,%2,%3};\n"
        : "+f"(d[0]), "+f"(d[1]), "+f"(d[2]), "+f"(d[3])
        : "r"(a[0]), "r"(a[1]), "r"(a[2]), "r"(a[3]), "r"(b[0]), "r"(b[1]));
}

__device__ __forceinline__ void cp16(float* s, const float* g) {
    unsigned sa = (unsigned)__cvta_generic_to_shared(s);
    asm volatile("cp.async.cg.shared.global [%0], [%1], 16;\n" :: "r"(sa), "l"(g));
}
#define CP_COMMIT() asm volatile("cp.async.commit_group;\n")
#define CP_WAIT1()  asm volatile("cp.async.wait_group 1;\n")
#define CP_WAIT0()  asm volatile("cp.async.wait_group 0;\n")

// ------------------- K1: fold BN into weights (tf32-rounded), transpose -------------------
__global__ void fold_kernel(const float* __restrict__ w0, const float* __restrict__ b0,
                            const float* __restrict__ g0, const float* __restrict__ be0,
                            const float* __restrict__ m0, const float* __restrict__ v0,
                            const float* __restrict__ w1, const float* __restrict__ b1,
                            const float* __restrict__ g1, const float* __restrict__ be1,
                            const float* __restrict__ m1, const float* __restrict__ v1) {
    int t = blockIdx.x * blockDim.x + threadIdx.x;
    if (t < CH * CIN) {
        int o = t / CIN, c = t % CIN;
        float s = g0[o] * rsqrtf(v0[o] + 1e-5f);
        g_W0t[c * CH + o] = cvt_tf32(w0[t] * s);
    }
    if (t < CH * CH) {
        int o = t / CH, c = t % CH;
        float s = g1[o] * rsqrtf(v1[o] + 1e-5f);
        g_W1t[c * CH + o] = cvt_tf32(w1[t] * s);
    }
    if (t < CH) {
        float s0 = g0[t] * rsqrtf(v0[t] + 1e-5f);
        g_b0f[t] = (b0[t] - m0[t]) * s0 + be0[t];
        float s1 = g1[t] * rsqrtf(v1[t] + 1e-5f);
        g_b1f[t] = (b1[t] - m1[t]) * s1 + be1[t];
    }
}

// ------------------- K2: pack xyz2 with norms -------------------
__global__ void pack_kernel(const float* __restrict__ xyz2) {
    int t = blockIdx.x * blockDim.x + threadIdx.x;
    if (t < BB * N2) {
        float x = xyz2[3 * t], y = xyz2[3 * t + 1], z = xyz2[3 * t + 2];
        g_xyz2n[t] = make_float4(x, y, z, x * x + y * y + z * z);
    }
}

// ------------------- K3: transpose points2 (B,C,N2) -> (B,N2,C) -------------------
__global__ void transpose_kernel(const float* __restrict__ p2) {
    __shared__ float tile[32][33];
    int b = blockIdx.z;
    int nb = blockIdx.x * 32, cb = blockIdx.y * 32;
    int tx = threadIdx.x, ty = threadIdx.y;  // (32, 8)
    #pragma unroll
    for (int i = 0; i < 32; i += 8)
        tile[ty + i][tx] = p2[((size_t)b * CC + cb + ty + i) * N2 + nb + tx];
    __syncthreads();
    #pragma unroll
    for (int i = 0; i < 32; i += 8)
        g_p2t[((size_t)b * N2 + nb + ty + i) * CC + cb + tx] = tile[tx][ty + i];
}

// ------------------- top-3 insertion -------------------
__device__ __forceinline__ void ins3(float s, int j,
                                     float& a0, float& a1, float& a2,
                                     int& i0, int& i1, int& i2) {
    if (s < a2) {
        if (s < a1) {
            a2 = a1; i2 = i1;
            if (s < a0) { a1 = a0; i1 = i0; a0 = s; i0 = j; }
            else        { a1 = s;  i1 = j; }
        } else { a2 = s; i2 = j; }
    }
}

// ------------------- K4a: segmented 3-NN partials -------------------
__global__ void __launch_bounds__(256) knn_part(const float* __restrict__ xyz1) {
    __shared__ float4 sP[SEGN];     // 8 KB
    int b = blockIdx.z, seg = blockIdx.y;
    int t = threadIdx.x;
    for (int i = t; i < SEGN; i += 256) sP[i] = g_xyz2n[b * N2 + seg * SEGN + i];
    __syncthreads();

    int q0 = blockIdx.x * 512 + t;
    int q1 = q0 + 256;
    const float* p0 = xyz1 + ((size_t)b * N1 + q0) * 3;
    const float* p1 = xyz1 + ((size_t)b * N1 + q1) * 3;
    float ax0 = -2.f * p0[0], ay0 = -2.f * p0[1], az0 = -2.f * p0[2];
    float ax1 = -2.f * p1[0], ay1 = -2.f * p1[1], az1 = -2.f * p1[2];

    float A0 = 3.0e38f, A1 = 3.0e38f, A2 = 3.0e38f;
    float B0 = 3.0e38f, B1 = 3.0e38f, B2 = 3.0e38f;
    int   I0 = 0, I1 = 0, I2 = 0, J0 = 0, J1 = 0, J2 = 0;

    #pragma unroll 8
    for (int j = 0; j < SEGN; j++) {
        float4 p = sP[j];
        float s0 = fmaf(ax0, p.x, fmaf(ay0, p.y, fmaf(az0, p.z, p.w)));
        ins3(s0, j, A0, A1, A2, I0, I1, I2);
        float s1 = fmaf(ax1, p.x, fmaf(ay1, p.y, fmaf(az1, p.z, p.w)));
        ins3(s1, j, B0, B1, B2, J0, J1, J2);
    }

    int base = seg * SEGN;
    size_t o0 = (size_t)(b * SEG + seg) * N1 + q0;
    size_t o1 = (size_t)(b * SEG + seg) * N1 + q1;
    g_pd[o0] = make_float4(A0, A1, A2, 0.f);
    g_pi[o0] = make_int4(base + I0, base + I1, base + I2, 0);
    g_pd[o1] = make_float4(B0, B1, B2, 0.f);
    g_pi[o1] = make_int4(base + J0, base + J1, base + J2, 0);
}

// ------------------- K4b: merge partials, compute interp weights -------------------
__global__ void knn_merge(const float* __restrict__ xyz1) {
    int t = blockIdx.x * blockDim.x + threadIdx.x;   // 0 .. BB*N1
    if (t >= BB * N1) return;
    int b = t / N1, q = t % N1;

    float A0 = 3.0e38f, A1 = 3.0e38f, A2 = 3.0e38f;
    int   I0 = 0, I1 = 0, I2 = 0;
    #pragma unroll
    for (int s = 0; s < SEG; s++) {
        size_t o = (size_t)(b * SEG + s) * N1 + q;
        float4 d = g_pd[o];
        int4   i = g_pi[o];
        ins3(d.x, i.x, A0, A1, A2, I0, I1, I2);
        ins3(d.y, i.y, A0, A1, A2, I0, I1, I2);
        ins3(d.z, i.z, A0, A1, A2, I0, I1, I2);
    }
    float x = xyz1[3 * t], y = xyz1[3 * t + 1], z = xyz1[3 * t + 2];
    float nq = x * x + y * y + z * z;
    float w0 = 1.f / (nq + A0), w1 = 1.f / (nq + A1), w2 = 1.f / (nq + A2);
    float inv = 1.f / (w0 + w1 + w2);
    g_w4[t] = make_float4(w0 * inv, w1 * inv, w2 * inv, 0.f);
    g_i4[t] = make_int4(I0, I1, I2, 0);
}

// ------------------- MLP building blocks -------------------
__device__ __forceinline__ void issue_w(int cc, int tid, float* sW) {
    const float* src = (cc < 12) ? (g_W0t + (size_t)cc * 32 * CH)
                                 : (g_W1t + (size_t)(cc - 12) * 32 * CH);
    float* dst = sW + (cc % NBUF) * SW_FLOATS;
    #pragma unroll
    for (int i = 0; i < 8; i++) {
        int f4 = tid + i * 256;          // 2048 float4 per chunk
        int kk = f4 >> 6, oc4 = f4 & 63;
        cp16(dst + kk * SWS + oc4 * 4, src + kk * CH + oc4 * 4);
    }
    CP_COMMIT();
}

__device__ __forceinline__ void gemm_chunk(const float* sWb, const float* sB,
                                           int warp, int lane, float acc[2][8][4]) {
    int grp = lane >> 2, tig = lane & 3, Rw = warp * 32;
    #pragma unroll
    for (int ks = 0; ks < 4; ks++) {
        int k8 = ks * 8;
        unsigned a[2][4], bf[8][2];
        const float* w0r = sWb + (k8 + tig) * SWS;
        const float* w4r = sWb + (k8 + tig + 4) * SWS;
        #pragma unroll
        for (int m = 0; m < 2; m++) {
            int rb = Rw + m * 16 + grp;
            a[m][0] = __float_as_uint(w0r[rb]);
            a[m][1] = __float_as_uint(w0r[rb + 8]);
            a[m][2] = __float_as_uint(w4r[rb]);
            a[m][3] = __float_as_uint(w4r[rb + 8]);
        }
        const float* x0r = sB + (k8 + tig) * SXS;
        const float* x4r = sB + (k8 + tig + 4) * SXS;
        #pragma unroll
        for (int j = 0; j < 8; j++) {
            int cb = j * 8 + grp;
            bf[j][0] = __float_as_uint(x0r[cb]);
            bf[j][1] = __float_as_uint(x4r[cb]);
        }
        #pragma unroll
        for (int m = 0; m < 2; m++)
            #pragma unroll
            for (int j = 0; j < 8; j++)
                mma8(acc[m][j], a[m], bf[j]);
    }
}

// ------------------- K5: fused concat + 2x (GEMM + BN + ReLU) + channel max -------------------
__global__ void __launch_bounds__(256, 1)
mlp_kernel(const float* __restrict__ points1, const float* __restrict__ pb1,
           float* __restrict__ out) {
    extern __shared__ float sm[];
    float* sX   = sm;                                   // [384][SXS]; reused as sY
    float* sW   = sm + SX_FLOATS;                       // 3 x [KC][SWS]
    int*   sOutI = (int*)(sm + SX_FLOATS + NBUF * SW_FLOATS);  // [TN]

    int b  = blockIdx.y;
    int n0 = blockIdx.x * TN;
    int tid = threadIdx.x;
    int warp = tid >> 5, lane = tid & 31;
    int grp = lane >> 2, tig = lane & 3;
    int Rw = warp * 32;

    // prefetch first two W chunks while building X
    issue_w(0, tid, sW);
    issue_w(1, tid, sW);

    // ---- Phase A: build X tile (384 x 64) in smem ----
    for (int idx = tid; idx < CC * TN; idx += 256) {
        int c = idx >> 6, n = idx & 63;
        sX[c * SXS + n]         = cvt_tf32(points1[((size_t)b * CC + c) * N1 + n0 + n]);
        sX[(c + 256) * SXS + n] = cvt_tf32(pb1[((size_t)b * CC + c) * N1 + n0 + n]);
    }
    // fused section rows 128..255 (each warp handles 8 queries; coalesced row gathers)
    for (int qq = 0; qq < 8; qq++) {
        int q = warp * 8 + qq;
        int n = n0 + q;
        float4 wv = g_w4[b * N1 + n];
        int4   iv = g_i4[b * N1 + n];
        const float* r0 = &g_p2t[((size_t)b * N2 + iv.x) * CC];
        const float* r1 = &g_p2t[((size_t)b * N2 + iv.y) * CC];
        const float* r2 = &g_p2t[((size_t)b * N2 + iv.z) * CC];
        #pragma unroll
        for (int i = 0; i < 4; i++) {
            int c = lane + 32 * i;
            float v = wv.x * r0[c] + wv.y * r1[c] + wv.z * r2[c];
            sX[(128 + c) * SXS + q] = cvt_tf32(v);
        }
    }

    // ---- GEMM1: y0(256x64) = W0'(256x384) * X, pipelined over 12 chunks ----
    float acc[2][8][4];
    #pragma unroll
    for (int m = 0; m < 2; m++)
        #pragma unroll
        for (int j = 0; j < 8; j++)
            #pragma unroll
            for (int e = 0; e < 4; e++) acc[m][j][e] = 0.f;

    for (int cc = 0; cc < 12; cc++) {
        CP_WAIT1();
        __syncthreads();     // chunk cc visible to all; also covers Phase A at cc=0
        gemm_chunk(sW + (cc % NBUF) * SW_FLOATS, sX + cc * 32 * SXS, warp, lane, acc);
        issue_w(cc + 2, tid, sW);   // into buf[(cc+2)%3]: safe, all passed this iter's bar
    }

    // ---- epilogue 1: bias + ReLU -> sY (rows 0..255 of sX region) ----
    // No pre-bar needed: last chunk's compute reads only rows 352..383; sY is rows 0..255.
    {
        float bz[4];
        #pragma unroll
        for (int i = 0; i < 4; i++) bz[i] = g_b0f[Rw + grp + 8 * i];
        float* sY = sm;
        #pragma unroll
        for (int m = 0; m < 2; m++)
            #pragma unroll
            for (int j = 0; j < 8; j++) {
                int r0 = Rw + 16 * m + grp;
                int col = 8 * j + 2 * tig;
                sY[r0 * SXS + col]           = cvt_tf32(fmaxf(acc[m][j][0] + bz[2 * m], 0.f));
                sY[r0 * SXS + col + 1]       = cvt_tf32(fmaxf(acc[m][j][1] + bz[2 * m], 0.f));
                sY[(r0 + 8) * SXS + col]     = cvt_tf32(fmaxf(acc[m][j][2] + bz[2 * m + 1], 0.f));
                sY[(r0 + 8) * SXS + col + 1] = cvt_tf32(fmaxf(acc[m][j][3] + bz[2 * m + 1], 0.f));
            }
    }

    // ---- GEMM2: y1(256x64) = W1'(256x256) * y0, pipelined over 8 chunks ----
    float ac2[2][8][4];
    #pragma unroll
    for (int m = 0; m < 2; m++)
        #pragma unroll
        for (int j = 0; j < 8; j++)
            #pragma unroll
            for (int e = 0; e < 4; e++) ac2[m][j][e] = 0.f;

    for (int cc = 12; cc < NCHUNK; cc++) {
        if (cc < NCHUNK - 1) { CP_WAIT1(); } else { CP_WAIT0(); }
        __syncthreads();     // chunk cc + epilogue-1 sY visible to all
        gemm_chunk(sW + (cc % NBUF) * SW_FLOATS, sm + (cc - 12) * 32 * SXS, warp, lane, ac2);
        if (cc + 2 < NCHUNK) issue_w(cc + 2, tid, sW);
    }

    // ---- epilogue 2: bias + ReLU + max over 256 channels ----
    float bz1[4];
    #pragma unroll
    for (int i = 0; i < 4; i++) bz1[i] = g_b1f[Rw + grp + 8 * i];

    if (tid < TN) sOutI[tid] = 0;   // ReLU output >= 0 -> int 0 is valid identity
    __syncthreads();

    #pragma unroll
    for (int j = 0; j < 8; j++) {
        #pragma unroll
        for (int e = 0; e < 2; e++) {
            int col = 8 * j + 2 * tig + e;
            float v =    fmaxf(ac2[0][j][e]     + bz1[0], 0.f);
            v = fmaxf(v, fmaxf(ac2[0][j][e + 2] + bz1[1], 0.f));
            v = fmaxf(v, fmaxf(ac2[1][j][e]     + bz1[2], 0.f));
            v = fmaxf(v, fmaxf(ac2[1][j][e + 2] + bz1[3], 0.f));
            v = fmaxf(v, __shfl_xor_sync(0xffffffffu, v, 4));
            v = fmaxf(v, __shfl_xor_sync(0xffffffffu, v, 8));
            v = fmaxf(v, __shfl_xor_sync(0xffffffffu, v, 16));
            if (grp == 0) atomicMax(&sOutI[col], __float_as_int(v));
        }
    }
    __syncthreads();
    if (tid < TN) out[(size_t)b * N1 + n0 + tid] = __int_as_float(sOutI[tid]);
}

// ------------------- launch -------------------
extern "C" void kernel_launch(void* const* d_in, const int* in_sizes, int n_in,
                              void* d_out, int out_size) {
    const float* xyz1    = (const float*)d_in[0];
    const float* xyz2    = (const float*)d_in[1];
    const float* points2 = (const float*)d_in[2];
    const float* points1 = (const float*)d_in[3];
    const float* pb1     = (const float*)d_in[4];
    const float* w0  = (const float*)d_in[5];
    const float* b0  = (const float*)d_in[6];
    const float* g0  = (const float*)d_in[7];
    const float* be0 = (const float*)d_in[8];
    const float* m0  = (const float*)d_in[9];
    const float* v0  = (const float*)d_in[10];
    const float* w1  = (const float*)d_in[11];
    const float* b1  = (const float*)d_in[12];
    const float* g1  = (const float*)d_in[13];
    const float* be1 = (const float*)d_in[14];
    const float* m1  = (const float*)d_in[15];
    const float* v1  = (const float*)d_in[16];
    float* out = (float*)d_out;

    cudaFuncSetAttribute(mlp_kernel, cudaFuncAttributeMaxDynamicSharedMemorySize,
                         SMEM_MLP_BYTES);

    fold_kernel<<<(CH * CIN + 255) / 256, 256>>>(w0, b0, g0, be0, m0, v0,
                                                 w1, b1, g1, be1, m1, v1);
    pack_kernel<<<(BB * N2 + 255) / 256, 256>>>(xyz2);
    transpose_kernel<<<dim3(N2 / 32, CC / 32, BB), dim3(32, 8)>>>(points2);
    knn_part<<<dim3(N1 / 512, SEG, BB), 256>>>(xyz1);
    knn_merge<<<(BB * N1 + 255) / 256, 256>>>(xyz1);
    mlp_kernel<<<dim3(N1 / TN, BB), 256, SMEM_MLP_BYTES>>>(points1, pb1, out);
}